// round 2
// baseline (speedup 1.0000x reference)
#include <cuda_runtime.h>
#include <cuda_bf16.h>
#include <cstdint>
#include <math.h>

typedef unsigned long long ull;

// ---------------- device scratch (static; no runtime allocation) ----------------
__device__ float g_A1[64*64];
__device__ float g_A2[64*64];
__device__ float g_henc[4096UL*256*32];     // GNN out, (seq n=b*64+c, t, g)
__device__ float g_h0[4096UL*256*128];      // BiGRU L0 out, (n, t, dir*64+h)
__device__ float g_last[4096*128];          // L1 last-step concat (n, 128)
__device__ float g_dxg[64*256];             // decoder LSTM L1 const gates (b, 256)
__device__ float g_h1d[64UL*256*64];        // decoder LSTM L1 hidden seq

// ---------------- helpers ----------------
__device__ __forceinline__ void fma2(ull &acc, ull a, ull b){
    asm("fma.rn.f32x2 %0, %1, %2, %0;" : "+l"(acc) : "l"(a), "l"(b));
}
__device__ __forceinline__ float hsum2(ull a){
    float lo, hi; asm("mov.b64 {%0,%1}, %2;" : "=f"(lo), "=f"(hi) : "l"(a));
    return lo + hi;
}
__device__ __forceinline__ float sigf(float x){ return 1.f/(1.f + expf(-x)); }

// ---------------- K1: row softmax of adj1, adj2 ----------------
__global__ void k_softmax(const float* __restrict__ adj1, const float* __restrict__ adj2){
    int i = threadIdx.x;  // 64 threads, one row each
    for (int w = 0; w < 2; w++){
        const float* a = w ? adj2 : adj1;
        float* o = w ? g_A2 : g_A1;
        float mx = -1e30f;
        for (int j = 0; j < 64; j++) mx = fmaxf(mx, a[i*64+j]);
        float s = 0.f;
        for (int j = 0; j < 64; j++) s += expf(a[i*64+j] - mx);
        float inv = 1.f / s;
        for (int j = 0; j < 64; j++) o[i*64+j] = expf(a[i*64+j] - mx) * inv;
    }
}

// ---------------- K2: GNN encoder, one block per (b,t) ----------------
__global__ __launch_bounds__(256) void k_gnn(
    const float* __restrict__ x,
    const float* __restrict__ W1, const float* __restrict__ b1,
    const float* __restrict__ W2, const float* __restrict__ b2,
    const float* __restrict__ lng, const float* __restrict__ lnb)
{
    int bt = blockIdx.x;
    int b = bt >> 8, t = bt & 255;
    int tid = threadIdx.x;

    __shared__ float sA2[64*65];                  // padded, conflict-free
    __shared__ float sW2t[1024];                  // transposed W2: [k][g']
    __shared__ __align__(16) float sx[64];
    __shared__ float s1[64];
    __shared__ __align__(16) float sh1[2048];     // [j][g]
    __shared__ __align__(16) float sagg[2048];    // [i][g]
    __shared__ float sh2[64*33];                  // padded
    __shared__ float sW1[32], sb1[32], sb2[32], slg[32], slb[32];
    __shared__ float smean[64], srstd[64];

    for (int i = tid; i < 4096; i += 256) sA2[(i>>6)*65 + (i&63)] = g_A2[i];
    for (int i = tid; i < 1024; i += 256){ int gp = i>>5, k = i&31; sW2t[k*32+gp] = W2[i]; }
    if (tid < 64) sx[tid] = x[(size_t)bt*64 + tid];
    if (tid < 32){ sW1[tid]=W1[tid]; sb1[tid]=b1[tid]; sb2[tid]=b2[tid]; slg[tid]=lng[tid]; slb[tid]=lnb[tid]; }
    __syncthreads();

    // s1 = A1 @ x
    if (tid < 64){
        float s = 0.f; const float* a = g_A1 + tid*64;
        #pragma unroll 8
        for (int j = 0; j < 64; j++) s += a[j]*sx[j];
        s1[tid] = s;
    }
    __syncthreads();

    // h1[j][g] = relu(W1[g]*s1[j] + b1[g])
    for (int i = tid; i < 2048; i += 256){ int j = i>>5, g = i&31; sh1[i] = fmaxf(sW1[g]*s1[j] + sb1[g], 0.f); }
    __syncthreads();

    // agg[i][g] = sum_j A2[i][j] * h1[j][g]
    {
        int i = tid >> 2, g0 = (tid & 3) * 8;
        float4 a0 = {0,0,0,0}, a1 = {0,0,0,0};
        #pragma unroll 4
        for (int j = 0; j < 64; j++){
            float a = sA2[i*65 + j];
            float4 h0 = *(const float4*)(sh1 + j*32 + g0);
            float4 h1 = *(const float4*)(sh1 + j*32 + g0 + 4);
            a0.x += a*h0.x; a0.y += a*h0.y; a0.z += a*h0.z; a0.w += a*h0.w;
            a1.x += a*h1.x; a1.y += a*h1.y; a1.z += a*h1.z; a1.w += a*h1.w;
        }
        *(float4*)(sagg + i*32 + g0)     = a0;
        *(float4*)(sagg + i*32 + g0 + 4) = a1;
    }
    __syncthreads();

    // h2[i][g'] = relu(agg[i] . W2[g'] + b2[g'])
    #pragma unroll
    for (int q = 0; q < 8; q++){
        int idx = tid + (q << 8);
        int i = idx >> 5, gp = idx & 31;
        float acc = sb2[gp];
        #pragma unroll 8
        for (int k = 0; k < 32; k++) acc += sagg[i*32 + k] * sW2t[k*32 + gp];
        sh2[i*33 + gp] = fmaxf(acc, 0.f);
    }
    __syncthreads();

    // LayerNorm over g
    if (tid < 64){
        float m = 0.f;
        for (int g = 0; g < 32; g++) m += sh2[tid*33 + g];
        m *= (1.f/32.f);
        float v = 0.f;
        for (int g = 0; g < 32; g++){ float d = sh2[tid*33 + g] - m; v += d*d; }
        v *= (1.f/32.f);
        smean[tid] = m; srstd[tid] = rsqrtf(v + 1e-5f);
    }
    __syncthreads();

    for (int idx = tid; idx < 2048; idx += 256){
        int i = idx >> 5, g = idx & 31;
        float val = (sh2[i*33 + g] - smean[i]) * srstd[i] * slg[g] + slb[g];
        g_henc[(((size_t)b*64 + i)*256 + t)*32 + g] = val;
    }
}

// ---------------- K3: BiGRU layer 0, one block per (n, dir) ----------------
__global__ __launch_bounds__(192,2) void k_gru0(
    const float* __restrict__ Wih, const float* __restrict__ Whh,
    const float* __restrict__ bih, const float* __restrict__ bhh)
{
    int n = blockIdx.x, dir = blockIdx.y;
    int g = threadIdx.x;   // gate row 0..191
    __shared__ __align__(16) float sx[32];
    __shared__ __align__(16) float sh[64];
    __shared__ float sgi[192], sgh[192];

    ull wi[16], wh[32];
    {
        const ull* p = (const ull*)(Wih + ((size_t)dir*192 + g)*32);
        #pragma unroll
        for (int k = 0; k < 16; k++) wi[k] = p[k];
        const ull* q = (const ull*)(Whh + ((size_t)dir*192 + g)*64);
        #pragma unroll
        for (int k = 0; k < 32; k++) wh[k] = q[k];
    }
    float bi = bih[dir*192 + g], bh = bhh[dir*192 + g];

    const float* xbase = g_henc + (size_t)n*256*32;
    float* obase = g_h0 + (size_t)n*256*128 + dir*64;

    if (g < 64) sh[g] = 0.f;
    int t0 = dir ? 255 : 0;
    float xreg = (g < 32) ? xbase[t0*32 + g] : 0.f;

    for (int s = 0; s < 256; s++){
        int t = dir ? 255 - s : s;
        if (g < 32) sx[g] = xreg;
        __syncthreads();
        if (g < 32 && s < 255){
            int tn = dir ? 254 - s : s + 1;
            xreg = xbase[tn*32 + g];
        }
        const ulonglong2* x4 = (const ulonglong2*)sx;
        const ulonglong2* h4 = (const ulonglong2*)sh;
        ull a0 = 0, a1 = 0;
        #pragma unroll
        for (int k = 0; k < 8; k++){ ulonglong2 v = x4[k]; fma2(a0, wi[2*k], v.x); fma2(a1, wi[2*k+1], v.y); }
        ull b0 = 0, b1 = 0;
        #pragma unroll
        for (int k = 0; k < 16; k++){ ulonglong2 v = h4[k]; fma2(b0, wh[2*k], v.x); fma2(b1, wh[2*k+1], v.y); }
        sgi[g] = hsum2(a0) + hsum2(a1) + bi;
        sgh[g] = hsum2(b0) + hsum2(b1) + bh;
        __syncthreads();
        if (g < 64){
            float r  = sigf(sgi[g] + sgh[g]);
            float z  = sigf(sgi[64+g] + sgh[64+g]);
            float nn = tanhf(sgi[128+g] + r*sgh[128+g]);
            float h  = (1.f - z)*nn + z*sh[g];
            sh[g] = h;
            obase[t*128 + g] = h;
        }
    }
}

// ---------------- K4a: GRU layer 1 forward (only last h needed) ----------------
__global__ __launch_bounds__(384,1) void k_gru1f(
    const float* __restrict__ Wih, const float* __restrict__ Whh,
    const float* __restrict__ bih, const float* __restrict__ bhh)
{
    int n = blockIdx.x;
    int tid = threadIdx.x;
    bool isA = tid < 192;             // A: input proj (128); B: hidden proj (64)
    int g = isA ? tid : tid - 192;
    __shared__ __align__(16) float sx[128];
    __shared__ __align__(16) float sh[64];
    __shared__ float sgi[192], sgh[192];

    ull w[64];
    if (isA){
        const ull* p = (const ull*)(Wih + (size_t)g*128);       // dir 0
        #pragma unroll
        for (int k = 0; k < 64; k++) w[k] = p[k];
    } else {
        const ull* p = (const ull*)(Whh + (size_t)g*64);        // dir 0
        #pragma unroll
        for (int k = 0; k < 32; k++) w[k] = p[k];
    }
    float bias = isA ? bih[g] : bhh[g];

    const float* xbase = g_h0 + (size_t)n*256*128;
    if (tid < 64) sh[tid] = 0.f;
    float xreg = (tid < 128) ? xbase[tid] : 0.f;

    for (int t = 0; t < 256; t++){
        if (tid < 128) sx[tid] = xreg;
        __syncthreads();
        if (tid < 128 && t < 255) xreg = xbase[(size_t)(t+1)*128 + tid];
        ull a0 = 0, a1 = 0;
        if (isA){
            const ulonglong2* v4 = (const ulonglong2*)sx;
            #pragma unroll
            for (int k = 0; k < 32; k++){ ulonglong2 v = v4[k]; fma2(a0, w[2*k], v.x); fma2(a1, w[2*k+1], v.y); }
            sgi[g] = hsum2(a0) + hsum2(a1) + bias;
        } else {
            const ulonglong2* v4 = (const ulonglong2*)sh;
            #pragma unroll
            for (int k = 0; k < 16; k++){ ulonglong2 v = v4[k]; fma2(a0, w[2*k], v.x); fma2(a1, w[2*k+1], v.y); }
            sgh[g] = hsum2(a0) + hsum2(a1) + bias;
        }
        __syncthreads();
        if (tid < 64){
            float r  = sigf(sgi[tid] + sgh[tid]);
            float z  = sigf(sgi[64+tid] + sgh[64+tid]);
            float nn = tanhf(sgi[128+tid] + r*sgh[128+tid]);
            float h  = (1.f - z)*nn + z*sh[tid];
            sh[tid] = h;
            if (t == 255) g_last[n*128 + tid] = h;
        }
    }
}

// ---------------- K4b: GRU layer 1 backward = single step from h0=0 ----------------
__global__ __launch_bounds__(192,2) void k_gru1b(
    const float* __restrict__ Wih, const float* __restrict__ Whh,
    const float* __restrict__ bih, const float* __restrict__ bhh)
{
    int tid = threadIdx.x;   // gate row, dir 1
    __shared__ __align__(16) float sx[128];
    __shared__ float sgi[192];
    ull w[64];
    const ull* p = (const ull*)(Wih + 192UL*128 + (size_t)tid*128);
    #pragma unroll
    for (int k = 0; k < 64; k++) w[k] = p[k];
    float bias = bih[192 + tid];

    for (int it = 0; it < 64; it++){
        int n = blockIdx.x*64 + it;
        if (tid < 128) sx[tid] = g_h0[((size_t)n*256 + 255)*128 + tid];
        __syncthreads();
        ull a0 = 0, a1 = 0;
        const ulonglong2* v4 = (const ulonglong2*)sx;
        #pragma unroll
        for (int k = 0; k < 32; k++){ ulonglong2 v = v4[k]; fma2(a0, w[2*k], v.x); fma2(a1, w[2*k+1], v.y); }
        sgi[tid] = hsum2(a0) + hsum2(a1) + bias;
        __syncthreads();
        if (tid < 64){
            float r  = sigf(sgi[tid]      + bhh[192 + tid]);
            float z  = sigf(sgi[64 + tid] + bhh[192 + 64 + tid]);
            float nn = tanhf(sgi[128+tid] + r * bhh[192 + 128 + tid]);
            g_last[n*128 + 64 + tid] = (1.f - z)*nn;
        }
    }
}

// ---------------- K5: pooling + VAE head + decoder fc + LSTM-L1 const gates ----------------
__global__ __launch_bounds__(128) void k_head(
    const float* __restrict__ pool_W, const float* __restrict__ pool_b,
    const float* __restrict__ mu_W, const float* __restrict__ mu_b,
    const float* __restrict__ logv_W, const float* __restrict__ logv_b,
    const float* __restrict__ dec_W, const float* __restrict__ dec_b,
    const float* __restrict__ lstm_Wih, const float* __restrict__ lstm_bih,
    const float* __restrict__ lstm_bhh,
    float* __restrict__ out)
{
    int b = blockIdx.x, tid = threadIdx.x;
    __shared__ float slast[128], shp[32], smu[32], sdh[64];
    float s = 0.f;
    for (int c = 0; c < 64; c++) s += g_last[(b*64 + c)*128 + tid];
    slast[tid] = s * (1.f/64.f);
    __syncthreads();
    if (tid < 32){
        float acc = pool_b[tid];
        for (int k = 0; k < 128; k++) acc += pool_W[tid*128 + k] * slast[k];
        shp[tid] = fmaxf(acc, 0.f);
    }
    __syncthreads();
    if (tid < 32){
        float acc = mu_b[tid];
        for (int k = 0; k < 32; k++) acc += mu_W[tid*32 + k] * shp[k];
        smu[tid] = acc;
        out[64UL*256*64 + b*32 + tid] = acc;
    } else if (tid < 64){
        int j = tid - 32;
        float acc = logv_b[j];
        for (int k = 0; k < 32; k++) acc += logv_W[j*32 + k] * shp[k];
        out[64UL*256*64 + 2048 + b*32 + j] = acc;
    }
    __syncthreads();
    if (tid < 64){
        float acc = dec_b[tid];
        for (int k = 0; k < 32; k++) acc += dec_W[tid*32 + k] * smu[k];
        sdh[tid] = fmaxf(acc, 0.f);
    }
    __syncthreads();
    for (int gate = tid; gate < 256; gate += 128){
        float acc = lstm_bih[gate] + lstm_bhh[gate];   // layer 0
        for (int k = 0; k < 64; k++) acc += lstm_Wih[gate*64 + k] * sdh[k];
        g_dxg[b*256 + gate] = acc;
    }
}

// ---------------- K6: decoder LSTM layer 1 (constant input gates) ----------------
__global__ __launch_bounds__(256,1) void k_lstm1(const float* __restrict__ Whh)
{
    int b = blockIdx.x, tid = threadIdx.x;
    __shared__ __align__(16) float sh[64];
    __shared__ float sg[256];
    ull w[32];
    const ull* p = (const ull*)(Whh + (size_t)tid*64);   // layer 0
    #pragma unroll
    for (int k = 0; k < 32; k++) w[k] = p[k];
    float dxg = g_dxg[b*256 + tid];
    if (tid < 64) sh[tid] = 0.f;
    float c = 0.f;
    for (int t = 0; t < 256; t++){
        __syncthreads();
        ull a0 = 0, a1 = 0;
        const ulonglong2* v4 = (const ulonglong2*)sh;
        #pragma unroll
        for (int k = 0; k < 16; k++){ ulonglong2 v = v4[k]; fma2(a0, w[2*k], v.x); fma2(a1, w[2*k+1], v.y); }
        sg[tid] = hsum2(a0) + hsum2(a1) + dxg;
        __syncthreads();
        if (tid < 64){
            float i_ = sigf(sg[tid]), f_ = sigf(sg[64+tid]);
            float gg = tanhf(sg[128+tid]), o_ = sigf(sg[192+tid]);
            c = f_*c + i_*gg;
            float h = o_*tanhf(c);
            sh[tid] = h;
            g_h1d[((size_t)b*256 + t)*64 + tid] = h;
        }
    }
}

// ---------------- K7: decoder LSTM layer 2 + fused output projection ----------------
__global__ __launch_bounds__(256,1) void k_lstm2(
    const float* __restrict__ Wih, const float* __restrict__ Whh,
    const float* __restrict__ bih, const float* __restrict__ bhh,
    const float* __restrict__ out_W, const float* __restrict__ out_b,
    float* __restrict__ out)
{
    int b = blockIdx.x, tid = threadIdx.x;
    __shared__ __align__(16) float sx[64];
    __shared__ __align__(16) float sh[64];
    __shared__ float sg[256];
    __shared__ float soW[64*64];     // transposed: soW[k*64+c] = out_W[c*64+k]
    for (int i = tid; i < 4096; i += 256){ int c = i >> 6, k = i & 63; soW[k*64 + c] = out_W[i]; }
    ull wi[32], wh[32];
    const ull* p = (const ull*)(Wih + 256UL*64 + (size_t)tid*64);
    const ull* q = (const ull*)(Whh + 256UL*64 + (size_t)tid*64);
    #pragma unroll
    for (int k = 0; k < 32; k++){ wi[k] = p[k]; wh[k] = q[k]; }
    float bias = bih[256 + tid] + bhh[256 + tid];
    if (tid < 64) sh[tid] = 0.f;
    float c = 0.f;
    float ob = (tid >= 64 && tid < 128) ? out_b[tid - 64] : 0.f;
    const float* xb = g_h1d + (size_t)b*256*64;
    for (int t = 0; t < 256; t++){
        if (tid < 64) sx[tid] = xb[t*64 + tid];
        __syncthreads();
        ull a0 = 0, a1 = 0;
        const ulonglong2* x4 = (const ulonglong2*)sx;
        const ulonglong2* h4 = (const ulonglong2*)sh;
        #pragma unroll
        for (int k = 0; k < 16; k++){ ulonglong2 v = x4[k]; fma2(a0, wi[2*k], v.x); fma2(a1, wi[2*k+1], v.y); }
        #pragma unroll
        for (int k = 0; k < 16; k++){ ulonglong2 v = h4[k]; fma2(a0, wh[2*k], v.x); fma2(a1, wh[2*k+1], v.y); }
        sg[tid] = hsum2(a0) + hsum2(a1) + bias;
        __syncthreads();
        if (tid < 64){
            float i_ = sigf(sg[tid]), f_ = sigf(sg[64+tid]);
            float gg = tanhf(sg[128+tid]), o_ = sigf(sg[192+tid]);
            c = f_*c + i_*gg;
            sh[tid] = o_*tanhf(c);
        }
        __syncthreads();
        if (tid >= 64 && tid < 128){
            int cc = tid - 64;
            float acc = ob;
            #pragma unroll 8
            for (int k = 0; k < 64; k++) acc += soW[k*64 + cc] * sh[k];
            out[((size_t)b*256 + t)*64 + cc] = acc;
        }
    }
}

extern "C" void kernel_launch(void* const* d_in, const int* in_sizes, int n_in,
                              void* d_out, int out_size)
{
    const float* x      = (const float*)d_in[0];
    const float* adj1   = (const float*)d_in[1];
    const float* W1     = (const float*)d_in[2];
    const float* b1     = (const float*)d_in[3];
    const float* adj2   = (const float*)d_in[4];
    const float* W2     = (const float*)d_in[5];
    const float* b2     = (const float*)d_in[6];
    const float* ln_g   = (const float*)d_in[7];
    const float* ln_b   = (const float*)d_in[8];
    const float* g0Wih  = (const float*)d_in[9];
    const float* g0Whh  = (const float*)d_in[10];
    const float* g0bih  = (const float*)d_in[11];
    const float* g0bhh  = (const float*)d_in[12];
    const float* g1Wih  = (const float*)d_in[13];
    const float* g1Whh  = (const float*)d_in[14];
    const float* g1bih  = (const float*)d_in[15];
    const float* g1bhh  = (const float*)d_in[16];
    const float* pool_W = (const float*)d_in[17];
    const float* pool_b = (const float*)d_in[18];
    const float* mu_W   = (const float*)d_in[19];
    const float* mu_b   = (const float*)d_in[20];
    const float* logv_W = (const float*)d_in[21];
    const float* logv_b = (const float*)d_in[22];
    const float* dec_W  = (const float*)d_in[23];
    const float* dec_b  = (const float*)d_in[24];
    const float* lWih   = (const float*)d_in[25];
    const float* lWhh   = (const float*)d_in[26];
    const float* lbih   = (const float*)d_in[27];
    const float* lbhh   = (const float*)d_in[28];
    const float* out_W  = (const float*)d_in[29];
    const float* out_b  = (const float*)d_in[30];
    float* out = (float*)d_out;

    k_softmax<<<1, 64>>>(adj1, adj2);
    k_gnn<<<16384, 256>>>(x, W1, b1, W2, b2, ln_g, ln_b);
    k_gru0<<<dim3(4096, 2), 192>>>(g0Wih, g0Whh, g0bih, g0bhh);
    k_gru1f<<<4096, 384>>>(g1Wih, g1Whh, g1bih, g1bhh);
    k_gru1b<<<64, 192>>>(g1Wih, g1Whh, g1bih, g1bhh);
    k_head<<<64, 128>>>(pool_W, pool_b, mu_W, mu_b, logv_W, logv_b,
                        dec_W, dec_b, lWih, lbih, lbhh, out);
    k_lstm1<<<64, 256>>>(lWhh);
    k_lstm2<<<64, 256>>>(lWih, lWhh, lbih, lbhh, out_W, out_b, out);
}